// round 3
// baseline (speedup 1.0000x reference)
#include <cuda_runtime.h>

#define TT 4096
#define BB 128
#define CC 46
#define LL 43
#define CHUNKS 32           /* TT / 128 */
#define NEGF (-1e30f)
#define NINF (-3.4e38f)

// ---------------- scratch (static device globals; no allocation) ----------------
__device__ float4 g_cmats[BB * CHUNKS];   // per-(batch,chunk) semiring product
__device__ float  g_numpart[BB * CHUNKS];
__device__ float  g_res[BB];
__device__ int    g_cnt[BB];              // zero-init (BSS); self-resetting
__device__ int    g_cnt_all;              // zero-init; self-resetting

// ---------------- semiring helpers ----------------
__device__ __forceinline__ float lse2f(float x, float y) {
    float mx = fmaxf(x, y);
    float mn = fminf(x, y);
    return mx + __logf(1.0f + __expf(mn - mx));
}

// C = A (later) (x) B (earlier) in (logsumexp,+) semiring. x=00,y=01,z=10,w=11
__device__ __forceinline__ float4 semimul(const float4 A, const float4 B) {
    float4 C;
    C.x = lse2f(A.x + B.x, A.y + B.z);
    C.y = lse2f(A.x + B.y, A.y + B.w);
    C.z = lse2f(A.z + B.x, A.w + B.z);
    C.w = lse2f(A.z + B.y, A.w + B.w);
    return C;
}

__device__ __forceinline__ float4 shfl_down4(float4 v, int s) {
    float4 r;
    r.x = __shfl_down_sync(0xffffffffu, v.x, s, 32);
    r.y = __shfl_down_sync(0xffffffffu, v.y, s, 32);
    r.z = __shfl_down_sync(0xffffffffu, v.z, s, 32);
    r.w = __shfl_down_sync(0xffffffffu, v.w, s, 32);
    return r;
}

// ---------------- k1: fully fused kernel ----------------
// grid (TT/128, BB), block 128 threads, thread = one timestep.
__global__ void __launch_bounds__(128) k1_main(
    const float* __restrict__ lp,
    const float* __restrict__ dp,
    const int* __restrict__ lens,
    const int* __restrict__ labels,
    float* __restrict__ out)
{
    __shared__ float  tile[128 * CC];     // 23552 B
    __shared__ float  w0s[CC], w1s[CC];
    __shared__ float  scs[2];             // [0]=s_0I, [1]=s_1I
    __shared__ float4 msm[128];
    __shared__ float  warpT[4];

    const int tid  = threadIdx.x;
    const int lane = tid & 31;
    const int wid  = tid >> 5;
    const int b    = blockIdx.y;
    const int tb   = blockIdx.x * 128;

    float lz0 = 0.f;   // warp 0 keeps this live for the closer path (s_fin)

    // --- warp 0: recompute softmax weights from den_params (L2 broadcast) ---
    if (wid == 0) {
        float a  = dp[lane];
        float bb = (lane + 32 < CC) ? dp[lane + 32] : NINF;
        float m = fmaxf(a, bb);
#pragma unroll
        for (int o = 16; o; o >>= 1) m = fmaxf(m, __shfl_xor_sync(0xffffffffu, m, o));
        float s = __expf(a - m) + __expf(bb - m);
#pragma unroll
        for (int o = 16; o; o >>= 1) s += __shfl_xor_sync(0xffffffffu, s, o);
        lz0 = m + __logf(s);
        // g1 over dp[46..89] (44 entries)
        float a1 = (lane < LL + 1) ? dp[CC + lane] : NINF;
        float b1 = (lane + 32 < LL + 1) ? dp[CC + lane + 32] : NINF;
        float m1 = fmaxf(a1, b1);
#pragma unroll
        for (int o = 16; o; o >>= 1) m1 = fmaxf(m1, __shfl_xor_sync(0xffffffffu, m1, o));
        float s1 = __expf(a1 - m1) + __expf(b1 - m1);
#pragma unroll
        for (int o = 16; o; o >>= 1) s1 += __shfl_xor_sync(0xffffffffu, s1, o);
        const float lz1 = m1 + __logf(s1);

#pragma unroll
        for (int c = lane; c < CC; c += 32) {
            float w0 = 0.f, w1 = 0.f;
            if (c == 1) w0 = __expf(dp[0] - lz0);          // exp(s_O) folded into S0
            if (c >= 3) {
                w0 = __expf(dp[c - 2] - lz0);              // exp(s0_lab[c-3])
                w1 = __expf(dp[CC + c - 2] - lz1);         // exp(s1_lab[c-3])
            }
            w0s[c] = w0; w1s[c] = w1;
        }
        if (lane == 0) {
            scs[0] = dp[LL + 1] - lz0;   // s_0I
            scs[1] = dp[CC] - lz1;       // s_1I
        }
    }

    // --- coalesced float4 staging: 128 rows x 46 floats = 1472 float4 ---
    const float4* __restrict__ src = (const float4*)(lp + ((size_t)b * TT + tb) * CC);
    float4* dst = (float4*)tile;
#pragma unroll
    for (int i = 0; i < 11; i++) dst[tid + i * 128] = src[tid + i * 128];
    {
        int i = tid + 11 * 128;
        if (i < 1472) dst[i] = src[i];
    }
    __syncthreads();

    // per-thread row: 23 float2 LDS, stride 46 floats -> conflict-free
    float v[CC];
    const float2* r2 = (const float2*)(tile + tid * CC);
#pragma unroll
    for (int i = 0; i < 23; i++) { float2 q = r2[i]; v[2 * i] = q.x; v[2 * i + 1] = q.y; }

    // shared max over weighted columns {1, 3..45}
    float m = v[1];
#pragma unroll
    for (int c = 3; c < CC; c++) m = fmaxf(m, v[c]);

    float S0 = __expf(v[1] - m) * w0s[1];
    float S1 = 0.f;
#pragma unroll
    for (int c = 3; c < CC; c++) {
        float e = __expf(v[c] - m);
        S0 = fmaf(e, w0s[c], S0);
        S1 = fmaf(e, w1s[c], S1);
    }

    const float M00 = m + __logf(S0);
    const float M01 = m + __logf(S1);
    const float lp2 = v[2];
    const float M10 = scs[0] + lp2;
    const float M11 = scs[1] + lp2;

    const int  t     = tb + tid;
    const bool valid = t < lens[b];
    const int  lab   = labels[(size_t)b * TT + t];
    float tok        = valid ? tile[tid * CC + lab] : 0.f;

    msm[tid] = valid ? make_float4(M00, M01, M10, M11)
                     : make_float4(0.f, NEGF, NEGF, 0.f);   // semiring identity

    // masked token-logprob warp sum (cheap ALU)
#pragma unroll
    for (int o = 16; o; o >>= 1) tok += __shfl_xor_sync(0xffffffffu, tok, o);
    if (lane == 0) warpT[wid] = tok;
    __syncthreads();

    // --- warp 0 only: dense fold of 128 matrices ---
    if (wid == 0) {
        const float4* mm = msm + 4 * lane;
        float4 M = mm[0];
        M = semimul(mm[1], M);
        M = semimul(mm[2], M);
        M = semimul(mm[3], M);
#pragma unroll
        for (int s = 1; s < 32; s <<= 1) {
            float4 o4 = shfl_down4(M, s);
            if ((lane & (2 * s - 1)) == 0) M = semimul(o4, M);
        }

        const int slot = b * CHUNKS + blockIdx.x;
        int old = 0;
        if (lane == 0) {
            g_cmats[slot]   = M;
            g_numpart[slot] = warpT[0] + warpT[1] + warpT[2] + warpT[3];
            __threadfence();
            old = atomicAdd(&g_cnt[b], 1);
        }
        old = __shfl_sync(0xffffffffu, old, 0);

        // --- closer for this batch: fold 32 chunk matrices ---
        if (old == CHUNKS - 1) {
            __threadfence();
            float4 P = g_cmats[b * CHUNKS + lane];
            float  np = g_numpart[b * CHUNKS + lane];
#pragma unroll
            for (int s = 1; s < 32; s <<= 1) {
                float4 o4 = shfl_down4(P, s);
                if ((lane & (2 * s - 1)) == 0) P = semimul(o4, P);
            }
#pragma unroll
            for (int o = 16; o; o >>= 1) np += __shfl_xor_sync(0xffffffffu, np, o);

            int old2 = 0;
            if (lane == 0) {
                const float s_fin = dp[LL + 2] - lz0;
                const float den = lse2f(P.x, P.y + NEGF) + s_fin;  // alpha0=[0,NEG]
                g_res[b] = np - den;
                g_cnt[b] = 0;                 // reset for next graph replay
                __threadfence();
                old2 = atomicAdd(&g_cnt_all, 1);
            }
            old2 = __shfl_sync(0xffffffffu, old2, 0);

            // --- global closer: sum 128 batch results ---
            if (old2 == BB - 1) {
                __threadfence();
                float s = g_res[lane] + g_res[lane + 32] + g_res[lane + 64] + g_res[lane + 96];
#pragma unroll
                for (int o = 16; o; o >>= 1) s += __shfl_xor_sync(0xffffffffu, s, o);
                if (lane == 0) {
                    out[0] = s;
                    g_cnt_all = 0;            // reset for next graph replay
                }
            }
        }
    }
}

// ---------------- launcher ----------------
extern "C" void kernel_launch(void* const* d_in, const int* in_sizes, int n_in,
                              void* d_out, int out_size) {
    const float* lp     = (const float*)d_in[0];  // (B,T,C) float32
    const float* dp     = (const float*)d_in[1];  // (2L+4,) float32
    const int*   lens   = (const int*)d_in[2];    // (B,) int32
    const int*   labels = (const int*)d_in[3];    // (B,T) int32

    dim3 grid(TT / 128, BB);
    k1_main<<<grid, 128>>>(lp, dp, lens, labels, (float*)d_out);
}

// round 4
// speedup vs baseline: 1.0811x; 1.0811x over previous
#include <cuda_runtime.h>

#define TT 4096
#define BB 128
#define CC 46
#define LL 43
#define CHUNKS 32           /* TT / 128 */
#define NINF (-3.4e38f)

// ---------------- scratch (static device globals; no allocation) ----------------
__device__ float4 g_cmats[BB * CHUNKS];   // per-(batch,chunk) normalized prob matrix
__device__ float  g_cscl[BB * CHUNKS];    // log-scale of that matrix
__device__ float  g_numpart[BB * CHUNKS];

// ---------------- scaled-probability semiring matrix ----------------
// value = exp(s) * P, P 2x2 row-major: x=00, y=01, z=10, w=11, entries normalized to max=1.
struct SMat { float4 p; float s; };

// C = A (later) * B (earlier): plain 2x2 matmul + renormalize. 8 FFMA + 2 MUFU.
__device__ __forceinline__ SMat smul(const SMat A, const SMat B) {
    SMat C;
    C.p.x = fmaf(A.p.x, B.p.x, A.p.y * B.p.z);
    C.p.y = fmaf(A.p.x, B.p.y, A.p.y * B.p.w);
    C.p.z = fmaf(A.p.z, B.p.x, A.p.w * B.p.z);
    C.p.w = fmaf(A.p.z, B.p.y, A.p.w * B.p.w);
    float mx = fmaxf(fmaxf(C.p.x, C.p.y), fmaxf(C.p.z, C.p.w));
    float r  = __fdividef(1.0f, mx);          // MUFU rcp
    C.p.x *= r; C.p.y *= r; C.p.z *= r; C.p.w *= r;
    C.s = A.s + B.s + __logf(mx);             // MUFU lg2
    return C;
}

__device__ __forceinline__ SMat shfl_down_m(const SMat v, int s, int w) {
    SMat r;
    r.p.x = __shfl_down_sync(0xffffffffu, v.p.x, s, w);
    r.p.y = __shfl_down_sync(0xffffffffu, v.p.y, s, w);
    r.p.z = __shfl_down_sync(0xffffffffu, v.p.z, s, w);
    r.p.w = __shfl_down_sync(0xffffffffu, v.p.w, s, w);
    r.s   = __shfl_down_sync(0xffffffffu, v.s,   s, w);
    return r;
}

// ---------------- k1: main streaming kernel ----------------
// grid (TT/128, BB), block 128 threads, thread = one timestep.
__global__ void __launch_bounds__(128) k1_main(
    const float* __restrict__ lp,
    const float* __restrict__ dp,
    const int* __restrict__ lens,
    const int* __restrict__ labels)
{
    __shared__ float  tile[128 * CC];     // 23552 B
    __shared__ float2 wab[CC];            // (w0, w1) interleaved -> LDS.64
    __shared__ float  scs[2];             // [0]=s_0I, [1]=s_1I
    __shared__ float4 warpP[4];
    __shared__ float  warpS[4];
    __shared__ float  warpT[4];

    const int tid  = threadIdx.x;
    const int lane = tid & 31;
    const int wid  = tid >> 5;
    const int b    = blockIdx.y;
    const int tb   = blockIdx.x * 128;

    // --- warp 0: recompute softmax weights from den_params (L2 broadcast) ---
    if (wid == 0) {
        float a  = dp[lane];
        float bb = (lane + 32 < CC) ? dp[lane + 32] : NINF;
        float m = fmaxf(a, bb);
#pragma unroll
        for (int o = 16; o; o >>= 1) m = fmaxf(m, __shfl_xor_sync(0xffffffffu, m, o));
        float s = __expf(a - m) + __expf(bb - m);
#pragma unroll
        for (int o = 16; o; o >>= 1) s += __shfl_xor_sync(0xffffffffu, s, o);
        const float lz0 = m + __logf(s);
        float a1 = (lane < LL + 1) ? dp[CC + lane] : NINF;
        float b1 = (lane + 32 < LL + 1) ? dp[CC + lane + 32] : NINF;
        float m1 = fmaxf(a1, b1);
#pragma unroll
        for (int o = 16; o; o >>= 1) m1 = fmaxf(m1, __shfl_xor_sync(0xffffffffu, m1, o));
        float s1 = __expf(a1 - m1) + __expf(b1 - m1);
#pragma unroll
        for (int o = 16; o; o >>= 1) s1 += __shfl_xor_sync(0xffffffffu, s1, o);
        const float lz1 = m1 + __logf(s1);

#pragma unroll
        for (int c = lane; c < CC; c += 32) {
            float w0 = 0.f, w1 = 0.f;
            if (c == 1) w0 = __expf(dp[0] - lz0);          // exp(s_O) folded into S0
            if (c >= 3) {
                w0 = __expf(dp[c - 2] - lz0);              // exp(s0_lab[c-3])
                w1 = __expf(dp[CC + c - 2] - lz1);         // exp(s1_lab[c-3])
            }
            wab[c] = make_float2(w0, w1);
        }
        if (lane == 0) {
            scs[0] = dp[LL + 1] - lz0;   // s_0I
            scs[1] = dp[CC] - lz1;       // s_1I
        }
    }

    // --- coalesced float4 staging: 128 rows x 46 floats = 1472 float4 ---
    const float4* __restrict__ src = (const float4*)(lp + ((size_t)b * TT + tb) * CC);
    float4* dst = (float4*)tile;
#pragma unroll
    for (int i = 0; i < 11; i++) dst[tid + i * 128] = src[tid + i * 128];
    {
        int i = tid + 11 * 128;
        if (i < 1472) dst[i] = src[i];
    }
    __syncthreads();

    // per-thread row: 23 float2 LDS, stride 46 floats -> conflict-free
    float v[CC];
    const float2* r2 = (const float2*)(tile + tid * CC);
#pragma unroll
    for (int i = 0; i < 23; i++) { float2 q = r2[i]; v[2 * i] = q.x; v[2 * i + 1] = q.y; }

    // shared max over weighted columns {1, 3..45}
    float m = v[1];
#pragma unroll
    for (int c = 3; c < CC; c++) m = fmaxf(m, v[c]);

    float S0 = __expf(v[1] - m) * wab[1].x;
    float S1 = 0.f;
#pragma unroll
    for (int c = 3; c < CC; c++) {
        float e = __expf(v[c] - m);
        float2 w = wab[c];
        S0 = fmaf(e, w.x, S0);
        S1 = fmaf(e, w.y, S1);
    }

    const float lp2 = v[2];
    const int  t     = tb + tid;
    const bool valid = t < lens[b];
    const int  lab   = labels[(size_t)b * TT + t];
    float tok        = valid ? tile[tid * CC + lab] : 0.f;

    // per-timestep matrix in scaled-prob form (scale = m)
    SMat M;
    if (valid) {
        M.p = make_float4(S0, S1, __expf(scs[0] + lp2 - m), __expf(scs[1] + lp2 - m));
        M.s = m;
    } else {
        M.p = make_float4(1.f, 0.f, 0.f, 1.f);   // identity
        M.s = 0.f;
    }

    // masked token-logprob warp sum
#pragma unroll
    for (int o = 16; o; o >>= 1) tok += __shfl_xor_sync(0xffffffffu, tok, o);

    // --- warp-level ordered fold (later * earlier), cheap matmul semiring ---
#pragma unroll
    for (int s = 1; s < 32; s <<= 1) {
        SMat o = shfl_down_m(M, s, 32);
        if ((lane & (2 * s - 1)) == 0) M = smul(o, M);
    }
    if (lane == 0) { warpP[wid] = M.p; warpS[wid] = M.s; warpT[wid] = tok; }
    __syncthreads();

    if (tid == 0) {
        SMat A; A.p = warpP[0]; A.s = warpS[0];
#pragma unroll
        for (int wI = 1; wI < 4; wI++) {
            SMat Wm; Wm.p = warpP[wI]; Wm.s = warpS[wI];
            A = smul(Wm, A);                        // later warp (x) earlier
        }
        const int slot = b * CHUNKS + blockIdx.x;
        g_cmats[slot]   = A.p;
        g_cscl[slot]    = A.s;
        g_numpart[slot] = warpT[0] + warpT[1] + warpT[2] + warpT[3];
    }
}

// ---------------- k2: chunk reduce + den + num + global sum ----------------
// one block, 1024 threads; 8 lanes per batch (128 batches).
__global__ void __launch_bounds__(1024) k2_final(
    const float* __restrict__ dp, float* __restrict__ out)
{
    const int tid  = threadIdx.x;
    const int lane = tid & 31;
    const int wid  = tid >> 5;
    __shared__ float s_fin_sh;
    __shared__ float resv[BB];
    __shared__ float red[32];

    // warp 0: recompute lz0 -> s_fin
    if (wid == 0) {
        float a  = dp[lane];
        float bb = (lane + 32 < CC) ? dp[lane + 32] : NINF;
        float m = fmaxf(a, bb);
#pragma unroll
        for (int o = 16; o; o >>= 1) m = fmaxf(m, __shfl_xor_sync(0xffffffffu, m, o));
        float s = __expf(a - m) + __expf(bb - m);
#pragma unroll
        for (int o = 16; o; o >>= 1) s += __shfl_xor_sync(0xffffffffu, s, o);
        if (lane == 0) s_fin_sh = dp[LL + 2] - (m + __logf(s));
    }

    // 8 lanes per batch, each folds 4 consecutive chunks (ordered, time-ascending)
    const int b = tid >> 3;
    const int g = tid & 7;
    const float4* cm  = g_cmats   + b * CHUNKS + g * 4;
    const float*  cs  = g_cscl    + b * CHUNKS + g * 4;
    const float*  np4 = g_numpart + b * CHUNKS + g * 4;

    SMat M; M.p = cm[0]; M.s = cs[0];
#pragma unroll
    for (int j = 1; j < 4; j++) {
        SMat Nx; Nx.p = cm[j]; Nx.s = cs[j];
        M = smul(Nx, M);
    }
    float np = np4[0] + np4[1] + np4[2] + np4[3];

    // width-8 shuffle trees
#pragma unroll
    for (int s = 1; s < 8; s <<= 1) {
        SMat o = shfl_down_m(M, s, 8);
        if ((g & (2 * s - 1)) == 0) M = smul(o, M);
    }
#pragma unroll
    for (int s = 4; s; s >>= 1) np += __shfl_down_sync(0xffffffffu, np, s, 8);

    __syncthreads();   // s_fin_sh visible
    if (g == 0) {
        // alpha0 = [1, 0] (prob space): a0 = P00 -> den = s + log(P00) + s_fin
        float den = M.s + __logf(M.p.x) + s_fin_sh;
        resv[b] = np - den;
    }
    __syncthreads();

    float vv = (tid < BB) ? resv[tid] : 0.f;
#pragma unroll
    for (int o = 16; o; o >>= 1) vv += __shfl_xor_sync(0xffffffffu, vv, o);
    if (lane == 0) red[wid] = vv;
    __syncthreads();
    if (tid == 0) {
        float tsum = 0.f;
#pragma unroll
        for (int i = 0; i < 32; i++) tsum += red[i];
        out[0] = tsum;
    }
}

// ---------------- launcher ----------------
extern "C" void kernel_launch(void* const* d_in, const int* in_sizes, int n_in,
                              void* d_out, int out_size) {
    const float* lp     = (const float*)d_in[0];  // (B,T,C) float32
    const float* dp     = (const float*)d_in[1];  // (2L+4,) float32
    const int*   lens   = (const int*)d_in[2];    // (B,) int32
    const int*   labels = (const int*)d_in[3];    // (B,T) int32

    dim3 grid(TT / 128, BB);
    k1_main<<<grid, 128>>>(lp, dp, lens, labels);
    k2_final<<<1, 1024>>>(dp, (float*)d_out);
}